// round 4
// baseline (speedup 1.0000x reference)
#include <cuda_runtime.h>
#include <math.h>
#include <stdint.h>

#define BB     32
#define SS     577
#define HID    1408
#define H3     4224
#define NH     16
#define HD     88
#define BH     (BB*NH)      // 512
#define MROWS  (BB*SS)      // 18464
#define SPAD   640          // padded kv length for V (zeros beyond SS)
#define SCALEF 0.10660035817780521f   // 88^-0.5

// ---------------- scratch (static device globals; zero-initialized) ----------
__device__ float g_qkv[(size_t)MROWS * H3];          // 312 MB
__device__ float g_xr [(size_t)MROWS * HID];         // 104 MB (x rounded+permuted)
__device__ float g_wq [(size_t)HID * H3];            // 23.8 MB (w_qkv rounded)
__device__ float g_wo [(size_t)HID * HID];           // 7.9 MB  (w_o rounded)
__device__ float g_q  [(size_t)BH * SS * HD];        // 104 MB (rounded, d-perm)
__device__ float g_k  [(size_t)BH * SS * HD];        // 104 MB (rounded, d-perm)
__device__ float g_v  [(size_t)BH * HD * SPAD];      // 115 MB (rounded, transposed, s-perm)
__device__ float g_att[(size_t)MROWS * HID];         // 104 MB (rounded, k-perm)

// ---------------- helpers ----------------------------------------------------
__device__ __forceinline__ uint32_t smem_u32(const void* p) {
    return (uint32_t)__cvta_generic_to_shared(p);
}
__device__ __forceinline__ void cp_async16(uint32_t dst, const void* src) {
    asm volatile("cp.async.cg.shared.global [%0], [%1], 16;\n" :: "r"(dst), "l"(src));
}
__device__ __forceinline__ void cp_commit() {
    asm volatile("cp.async.commit_group;\n");
}
__device__ __forceinline__ uint32_t f2tf32(float f) {
    uint32_t u;
    asm("cvt.rna.tf32.f32 %0, %1;\n" : "=r"(u) : "f"(f));
    return u;
}
__device__ __forceinline__ float roundtf(float f) {
    return __uint_as_float(f2tf32(f));
}
__device__ __forceinline__ void mma_tf32(float c[4], const uint32_t a[4], const uint32_t b[2]) {
    asm volatile(
        "mma.sync.aligned.m16n8k8.row.col.f32.tf32.tf32.f32 "
        "{%0,%1,%2,%3}, {%4,%5,%6,%7}, {%8,%9}, {%0,%1,%2,%3};\n"
        : "+f"(c[0]), "+f"(c[1]), "+f"(c[2]), "+f"(c[3])
        : "r"(a[0]), "r"(a[1]), "r"(a[2]), "r"(a[3]), "r"(b[0]), "r"(b[1]));
}
// storage position of logical index d within its 8-block (pairs (t,t+4) adjacent)
__device__ __forceinline__ int pairpos(int d) {
    int a = d & ~7, t = d & 7;
    return a + ((t < 4) ? (2 * t) : (2 * t - 7));
}

// ---------------- prep: round weights (layout unchanged) ---------------------
__global__ __launch_bounds__(256) void round_copy4(
    const float* __restrict__ src, float* __restrict__ dst, int n4)
{
    int i = blockIdx.x * 256 + threadIdx.x;
    if (i >= n4) return;
    float4 v = ((const float4*)src)[i];
    v.x = roundtf(v.x); v.y = roundtf(v.y); v.z = roundtf(v.z); v.w = roundtf(v.w);
    ((float4*)dst)[i] = v;
}

// ---------------- prep: round + pair-permute x's K dim -----------------------
// out 8-block = {a.x,b.x,a.y,b.y, a.z,b.z,a.w,b.w} of in 8-block (a=first4,b=last4)
__global__ __launch_bounds__(256) void round_permute_x(
    const float* __restrict__ src, float* __restrict__ dst, int n8)
{
    int i = blockIdx.x * 256 + threadIdx.x;
    if (i >= n8) return;
    float4 a = ((const float4*)src)[2 * i];
    float4 b = ((const float4*)src)[2 * i + 1];
    float4 lo, hi;
    lo.x = roundtf(a.x); lo.y = roundtf(b.x); lo.z = roundtf(a.y); lo.w = roundtf(b.y);
    hi.x = roundtf(a.z); hi.y = roundtf(b.z); hi.z = roundtf(a.w); hi.w = roundtf(b.w);
    ((float4*)dst)[2 * i]     = lo;
    ((float4*)dst)[2 * i + 1] = hi;
}

// ---------------- tf32 tensor-core GEMM + bias (pre-rounded operands) --------
// A is pre-rounded AND pair-permuted along K; B pre-rounded (natural layout).
__global__ __launch_bounds__(256) void tf32_gemm_bias(
    const float* __restrict__ A, const float* __restrict__ Bm,
    const float* __restrict__ bias, float* __restrict__ C,
    int M, int N, int K)
{
    __shared__ float As[2][128][20];
    __shared__ float Bs[2][16][136];

    const int tid  = threadIdx.x;
    const int brow = blockIdx.y * 128;
    const int bcol = blockIdx.x * 128;
    const int wid  = tid >> 5;
    const int lane = tid & 31;
    const int g    = lane >> 2;
    const int t4   = lane & 3;
    const int wm   = (wid >> 2) * 64;
    const int wn   = (wid & 3) * 32;

    float acc[4][4][4];
#pragma unroll
    for (int mi = 0; mi < 4; mi++)
#pragma unroll
        for (int ni = 0; ni < 4; ni++)
#pragma unroll
            for (int r = 0; r < 4; r++) acc[mi][ni][r] = 0.f;

    const int nk = K / 16;

#define ISSUE_LOADS(s, k0)                                                     \
    {                                                                          \
        _Pragma("unroll")                                                      \
        for (int t = 0; t < 2; t++) {                                          \
            int chunk = tid + 256 * t;                                         \
            int arow = chunk >> 2;                                             \
            int akc  = (chunk & 3) * 4;                                        \
            uint32_t sa = smem_u32(&As[s][arow][akc]);                         \
            if (brow + arow < M) {                                             \
                cp_async16(sa, A + (size_t)(brow + arow) * K + (k0) + akc);    \
            } else {                                                           \
                *(float4*)&As[s][arow][akc] = make_float4(0.f, 0.f, 0.f, 0.f); \
            }                                                                  \
            int bkr = chunk >> 5;                                              \
            int bnc = (chunk & 31) * 4;                                        \
            cp_async16(smem_u32(&Bs[s][bkr][bnc]),                             \
                       Bm + (size_t)((k0) + bkr) * N + bcol + bnc);            \
        }                                                                      \
        cp_commit();                                                           \
    }

    ISSUE_LOADS(0, 0);

    for (int it = 0; it < nk; ++it) {
        const int s = it & 1;
        if (it + 1 < nk) {
            ISSUE_LOADS((it + 1) & 1, (it + 1) * 16);
            asm volatile("cp.async.wait_group 1;\n");
        } else {
            asm volatile("cp.async.wait_group 0;\n");
        }
        __syncthreads();

#pragma unroll
        for (int ks = 0; ks < 16; ks += 8) {
            uint32_t af[4][4], bf[4][2];
#pragma unroll
            for (int mi = 0; mi < 4; mi++) {
                int r0 = wm + mi * 16 + g;
                uint2 lo = *(const uint2*)&As[s][r0][ks + 2 * t4];       // (k, k+4)
                uint2 hi = *(const uint2*)&As[s][r0 + 8][ks + 2 * t4];
                af[mi][0] = lo.x; af[mi][2] = lo.y;
                af[mi][1] = hi.x; af[mi][3] = hi.y;
            }
#pragma unroll
            for (int ni = 0; ni < 4; ni++) {
                int c0 = wn + ni * 8 + g;
                bf[ni][0] = __float_as_uint(Bs[s][ks + t4][c0]);
                bf[ni][1] = __float_as_uint(Bs[s][ks + t4 + 4][c0]);
            }
#pragma unroll
            for (int mi = 0; mi < 4; mi++)
#pragma unroll
                for (int ni = 0; ni < 4; ni++)
                    mma_tf32(acc[mi][ni], af[mi], bf[ni]);
        }
        __syncthreads();
    }

#pragma unroll
    for (int mi = 0; mi < 4; mi++) {
#pragma unroll
        for (int ni = 0; ni < 4; ni++) {
            int r0 = brow + wm + mi * 16 + g;
            int c0 = bcol + wn + ni * 8 + t4 * 2;
            if (r0 < M) {
                C[(size_t)r0 * N + c0]     = acc[mi][ni][0] + bias[c0];
                C[(size_t)r0 * N + c0 + 1] = acc[mi][ni][1] + bias[c0 + 1];
            }
            if (r0 + 8 < M) {
                C[(size_t)(r0 + 8) * N + c0]     = acc[mi][ni][2] + bias[c0];
                C[(size_t)(r0 + 8) * N + c0 + 1] = acc[mi][ni][3] + bias[c0 + 1];
            }
        }
    }
#undef ISSUE_LOADS
}

// ---------------- RoPE -> Q,K rounded, d-pair-permuted [bh][s][88] ----------
__global__ __launch_bounds__(256) void rope_scatter_qk(
    const float* __restrict__ qkv,
    float* __restrict__ Q, float* __restrict__ K)
{
    const long long idx = (long long)blockIdx.x * blockDim.x + threadIdx.x;
    const long long total = (long long)BB * SS * NH * (HD / 2);
    if (idx >= total) return;

    int j = (int)(idx % (HD / 2));
    int h = (int)((idx / (HD / 2)) % NH);
    int s = (int)((idx / ((HD / 2) * NH)) % SS);
    int b = (int)(idx / ((long long)(HD / 2) * NH * SS));

    float c, sn;
    if (s == SS - 1) {
        c = 1.f; sn = 0.f;
    } else {
        int fx = s % 24;
        int fy = s / 24;
        int jj = (j < 22) ? j : (j - 22);
        int coord = (j < 22) ? (fx + 1) : (fy + 1);
        float inv = expf(-(float)jj * 0.41865183508982657f); // ln(1e4)/22
        float arg = (float)coord * inv;
        c  = cosf(arg);
        sn = sinf(arg);
    }

    const float* base = qkv + (size_t)(b * SS + s) * H3 + h * HD;
    float q0 = base[2 * j],       q1 = base[2 * j + 1];
    float k0 = base[HID + 2 * j], k1 = base[HID + 2 * j + 1];

    size_t o = ((size_t)(b * NH + h) * SS + s) * HD;
    int p0 = pairpos(2 * j), p1 = pairpos(2 * j + 1);
    Q[o + p0] = roundtf(q0 * c - q1 * sn);
    Q[o + p1] = roundtf(q0 * sn + q1 * c);
    K[o + p0] = roundtf(k0 * c - k1 * sn);
    K[o + p1] = roundtf(k0 * sn + k1 * c);
}

// ---------------- V: round + transpose to [bh][d][SPAD], s pair-permuted -----
__global__ __launch_bounds__(256) void v_transpose(
    const float* __restrict__ qkv, float* __restrict__ V)
{
    __shared__ float vt[64][89];

    const int bh = blockIdx.y;
    const int j0 = blockIdx.x * 64;
    const int b  = bh >> 4, h = bh & 15;
    const int tid = threadIdx.x;

    for (int idx = tid; idx < 64 * 22; idx += 256) {
        int row = idx / 22, c4 = (idx % 22) * 4;
        float4 v;
        if (j0 + row < SS)
            v = *(const float4*)(qkv + (size_t)(b * SS + j0 + row) * H3
                                 + 2 * HID + h * HD + c4);
        else
            v = make_float4(0.f, 0.f, 0.f, 0.f);
        vt[row][c4]     = v.x;
        vt[row][c4 + 1] = v.y;
        vt[row][c4 + 2] = v.z;
        vt[row][c4 + 3] = v.w;
    }
    __syncthreads();

    // write: consecutive threads -> consecutive output s positions (coalesced)
    for (int idx = tid; idx < HD * 64; idx += 256) {
        int d = idx >> 6, o = idx & 63;
        int ot = o & 7, oa = o & ~7;
        int srow = oa + ((o & 1) ? ((ot + 7) >> 1) : (ot >> 1));
        V[((size_t)bh * HD + d) * SPAD + j0 + o] = roundtf(vt[srow][d]);
    }
}

// ---------------- fused flash attention (tf32 mma, pre-rounded operands) -----
#define KSTRIDE 92
#define VSTRIDE 68
#define NT      10          // ceil(577/64)

__global__ __launch_bounds__(256, 1) void flash_attn(
    const float* __restrict__ Q, const float* __restrict__ K,
    const float* __restrict__ V, float* __restrict__ O)
{
    extern __shared__ float sm[];
    float (*Ks)[64][KSTRIDE] = (float (*)[64][KSTRIDE])sm;                  // 2 stages
    float (*Vs)[HD][VSTRIDE] = (float (*)[HD][VSTRIDE])(sm + 2 * 64 * KSTRIDE);

    const int bh  = blockIdx.y;
    const int q0  = blockIdx.x * 128;
    const int tid = threadIdx.x;
    const int wid = tid >> 5;
    const int lane = tid & 31;
    const int g   = lane >> 2;
    const int t4  = lane & 3;

    const float* Qb = Q + (size_t)bh * SS * HD;
    const float* Kb = K + (size_t)bh * SS * HD;
    const float* Vb = V + (size_t)bh * HD * SPAD;

    // preload Q fragments (pre-rounded, d-pair-permuted -> float2 loads)
    const int r0 = q0 + wid * 16 + g;
    const int r1 = r0 + 8;
    const int r0c = (r0 < SS) ? r0 : (SS - 1);
    const int r1c = (r1 < SS) ? r1 : (SS - 1);
    uint32_t qf[11][4];
#pragma unroll
    for (int kk = 0; kk < 11; kk++) {
        uint2 lo = *(const uint2*)(Qb + (size_t)r0c * HD + kk * 8 + 2 * t4);
        uint2 hi = *(const uint2*)(Qb + (size_t)r1c * HD + kk * 8 + 2 * t4);
        qf[kk][0] = lo.x; qf[kk][2] = lo.y;
        qf[kk][1] = hi.x; qf[kk][3] = hi.y;
    }

    float oacc[11][4];
#pragma unroll
    for (int ni = 0; ni < 11; ni++)
#pragma unroll
        for (int r = 0; r < 4; r++) oacc[ni][r] = 0.f;
    float m0 = -1e30f, m1 = -1e30f, l0 = 0.f, l1 = 0.f;

    // K tile: 64 rows x 88 (d-permuted), row-clamped. V tile: 88 rows x 64 s.
#define LOAD_TILE(s, j0v)                                                  \
    {                                                                      \
        for (int idx = tid; idx < 64 * 22; idx += 256) {                   \
            int row = idx / 22, c4 = (idx % 22) * 4;                       \
            int jr = (j0v) + row; jr = (jr < SS) ? jr : (SS - 1);          \
            cp_async16(smem_u32(&Ks[s][row][c4]), Kb + (size_t)jr * HD + c4); \
        }                                                                  \
        for (int idx = tid; idx < HD * 16; idx += 256) {                   \
            int d = idx >> 4, c4 = (idx & 15) * 4;                         \
            cp_async16(smem_u32(&Vs[s][d][c4]),                            \
                       Vb + (size_t)d * SPAD + (j0v) + c4);                \
        }                                                                  \
        cp_commit();                                                       \
    }

    LOAD_TILE(0, 0);

    for (int it = 0; it < NT; ++it) {
        const int s = it & 1;
        const int j0 = it * 64;
        if (it + 1 < NT) {
            LOAD_TILE((it + 1) & 1, (it + 1) * 64);
            asm volatile("cp.async.wait_group 1;\n");
        } else {
            asm volatile("cp.async.wait_group 0;\n");
        }
        __syncthreads();

        // ---- S = Q K^T (16 x 64 per warp) ----
        float sacc[8][4];
#pragma unroll
        for (int ni = 0; ni < 8; ni++)
#pragma unroll
            for (int r = 0; r < 4; r++) sacc[ni][r] = 0.f;

#pragma unroll
        for (int kk = 0; kk < 11; kk++) {
#pragma unroll
            for (int ni = 0; ni < 8; ni++) {
                uint2 kb = *(const uint2*)&Ks[s][ni * 8 + g][kk * 8 + 2 * t4];
                uint32_t bf[2] = {kb.x, kb.y};
                mma_tf32(sacc[ni], qf[kk], bf);
            }
        }

        // ---- scale + mask ----
#pragma unroll
        for (int ni = 0; ni < 8; ni++)
#pragma unroll
            for (int r = 0; r < 4; r++) sacc[ni][r] *= SCALEF;

        if (j0 + 64 > SS) {
#pragma unroll
            for (int ni = 0; ni < 8; ni++) {
                int c = j0 + ni * 8 + 2 * t4;
                if (c     >= SS) { sacc[ni][0] = -1e30f; sacc[ni][2] = -1e30f; }
                if (c + 1 >= SS) { sacc[ni][1] = -1e30f; sacc[ni][3] = -1e30f; }
            }
        }

        // ---- row stats (quad-local) ----
        float mx0 = -1e30f, mx1 = -1e30f;
#pragma unroll
        for (int ni = 0; ni < 8; ni++) {
            mx0 = fmaxf(mx0, fmaxf(sacc[ni][0], sacc[ni][1]));
            mx1 = fmaxf(mx1, fmaxf(sacc[ni][2], sacc[ni][3]));
        }
#pragma unroll
        for (int off = 1; off < 4; off <<= 1) {
            mx0 = fmaxf(mx0, __shfl_xor_sync(0xffffffffu, mx0, off));
            mx1 = fmaxf(mx1, __shfl_xor_sync(0xffffffffu, mx1, off));
        }

        float m0n = fmaxf(m0, mx0);
        float m1n = fmaxf(m1, mx1);
        float a0 = __expf(m0 - m0n);
        float a1 = __expf(m1 - m1n);

        float rs0 = 0.f, rs1 = 0.f;
#pragma unroll
        for (int ni = 0; ni < 8; ni++) {
            sacc[ni][0] = __expf(sacc[ni][0] - m0n);
            sacc[ni][1] = __expf(sacc[ni][1] - m0n);
            sacc[ni][2] = __expf(sacc[ni][2] - m1n);
            sacc[ni][3] = __expf(sacc[ni][3] - m1n);
            rs0 += sacc[ni][0] + sacc[ni][1];
            rs1 += sacc[ni][2] + sacc[ni][3];
        }
#pragma unroll
        for (int off = 1; off < 4; off <<= 1) {
            rs0 += __shfl_xor_sync(0xffffffffu, rs0, off);
            rs1 += __shfl_xor_sync(0xffffffffu, rs1, off);
        }
        l0 = l0 * a0 + rs0;
        l1 = l1 * a1 + rs1;
        m0 = m0n;
        m1 = m1n;

#pragma unroll
        for (int ni = 0; ni < 11; ni++) {
            oacc[ni][0] *= a0;
            oacc[ni][1] *= a0;
            oacc[ni][2] *= a1;
            oacc[ni][3] *= a1;
        }

        // ---- O += P V : permute P C-layout -> A-layout via quad shfl ----
        const int srcA = 4 * g + (t4 >> 1);
        const int srcB = srcA + 2;
        const bool odd = (t4 & 1);
#pragma unroll
        for (int kk = 0; kk < 8; kk++) {
            float v00 = __shfl_sync(0xffffffffu, sacc[kk][0], srcA);
            float v01 = __shfl_sync(0xffffffffu, sacc[kk][1], srcA);
            float v20 = __shfl_sync(0xffffffffu, sacc[kk][2], srcA);
            float v21 = __shfl_sync(0xffffffffu, sacc[kk][3], srcA);
            float w00 = __shfl_sync(0xffffffffu, sacc[kk][0], srcB);
            float w01 = __shfl_sync(0xffffffffu, sacc[kk][1], srcB);
            float w20 = __shfl_sync(0xffffffffu, sacc[kk][2], srcB);
            float w21 = __shfl_sync(0xffffffffu, sacc[kk][3], srcB);
            uint32_t af[4];
            af[0] = f2tf32(odd ? v01 : v00);   // row g,   kv t4
            af[1] = f2tf32(odd ? v21 : v20);   // row g+8, kv t4
            af[2] = f2tf32(odd ? w01 : w00);   // row g,   kv t4+4
            af[3] = f2tf32(odd ? w21 : w20);   // row g+8, kv t4+4
#pragma unroll
            for (int ni = 0; ni < 11; ni++) {
                uint2 vb = *(const uint2*)&Vs[s][ni * 8 + g][kk * 8 + 2 * t4];
                uint32_t bf[2] = {vb.x, vb.y};
                mma_tf32(oacc[ni], af, bf);
            }
        }
        __syncthreads();
    }

    // ---- normalize + store rounded, K-pair-permuted, to [b, s, h*88 + d] ----
    const int b = bh >> 4, h = bh & 15;
    const float il0 = 1.f / l0;
    const float il1 = 1.f / l1;
    const int P1[4] = {0, 4, 1, 5};    // pos of col 2*t4 within 8-block
    const int P2[4] = {2, 6, 3, 7};    // pos of col 2*t4+1
    if (r0 < SS) {
        float* o = O + (size_t)(b * SS + r0) * HID + h * HD;
#pragma unroll
        for (int ni = 0; ni < 11; ni++) {
            o[ni * 8 + P1[t4]] = roundtf(oacc[ni][0] * il0);
            o[ni * 8 + P2[t4]] = roundtf(oacc[ni][1] * il0);
        }
    }
    if (r1 < SS) {
        float* o = O + (size_t)(b * SS + r1) * HID + h * HD;
#pragma unroll
        for (int ni = 0; ni < 11; ni++) {
            o[ni * 8 + P1[t4]] = roundtf(oacc[ni][2] * il1);
            o[ni * 8 + P2[t4]] = roundtf(oacc[ni][3] * il1);
        }
    }
#undef LOAD_TILE
}

// ---------------- launch -----------------------------------------------------
extern "C" void kernel_launch(void* const* d_in, const int* in_sizes, int n_in,
                              void* d_out, int out_size)
{
    const float* x     = (const float*)d_in[0];
    const float* w_qkv = (const float*)d_in[1];
    const float* b_qkv = (const float*)d_in[2];
    const float* w_o   = (const float*)d_in[3];
    const float* b_o   = (const float*)d_in[4];
    float* out = (float*)d_out;

    float *qkv, *xr, *wq, *wo, *q, *k, *v, *att;
    cudaGetSymbolAddress((void**)&qkv, g_qkv);
    cudaGetSymbolAddress((void**)&xr,  g_xr);
    cudaGetSymbolAddress((void**)&wq,  g_wq);
    cudaGetSymbolAddress((void**)&wo,  g_wo);
    cudaGetSymbolAddress((void**)&q,   g_q);
    cudaGetSymbolAddress((void**)&k,   g_k);
    cudaGetSymbolAddress((void**)&v,   g_v);
    cudaGetSymbolAddress((void**)&att, g_att);

    // 0) prep: round weights; round+permute x
    {
        int n4 = HID * H3 / 4;
        round_copy4<<<(n4 + 255) / 256, 256>>>(w_qkv, wq, n4);
        n4 = HID * HID / 4;
        round_copy4<<<(n4 + 255) / 256, 256>>>(w_o, wo, n4);
        int n8 = MROWS * HID / 8;
        round_permute_x<<<(n8 + 255) / 256, 256>>>(x, xr, n8);
    }

    // 1) QKV projection (tf32 tensor cores, no in-kernel cvt)
    tf32_gemm_bias<<<dim3(H3 / 128, (MROWS + 127) / 128), 256>>>(
        xr, wq, b_qkv, qkv, MROWS, H3, HID);

    // 2) RoPE Q,K (rounded, d-permuted) + V transpose (rounded, s-permuted)
    {
        long long total = (long long)BB * SS * NH * (HD / 2);
        rope_scatter_qk<<<(int)((total + 255) / 256), 256>>>(qkv, q, k);
        v_transpose<<<dim3(NT, BH), 256>>>(qkv, v);
    }

    // 3) fused flash attention -> att (rounded, K-permuted)
    {
        const int smem_bytes = (2 * 64 * KSTRIDE + 2 * HD * VSTRIDE) * 4;
        cudaFuncSetAttribute(flash_attn,
                             cudaFuncAttributeMaxDynamicSharedMemorySize,
                             smem_bytes);
        flash_attn<<<dim3((SS + 127) / 128, BH), 256, smem_bytes>>>(q, k, v, att);
    }

    // 4) output projection (tf32 tensor cores)
    tf32_gemm_bias<<<dim3(HID / 128, (MROWS + 127) / 128), 256>>>(
        att, wo, b_o, out, MROWS, HID, HID);
}

// round 5
// speedup vs baseline: 2.2020x; 2.2020x over previous
#include <cuda_runtime.h>
#include <cuda_fp16.h>
#include <math.h>
#include <stdint.h>

#define BB     32
#define SS     577
#define HID    1408
#define H3     4224
#define NH     16
#define HD     88
#define BH     (BB*NH)      // 512
#define MROWS  (BB*SS)      // 18464
#define K2Q    (HID/2)      // 704  (k-pairs)
#define D2     48           // padded per-head d-pairs (96 d)
#define SPAD   640
#define KV2    (SPAD/2)     // 320
#define NT     10           // ceil(577/64)
#define SCALEF 0.10660035817780521f   // 88^-0.5

// ---------------- scratch (static device globals; zero-initialized) ----------
__device__ float    g_qkv[(size_t)MROWS * H3];      // 312 MB fp32
__device__ uint32_t g_xr [(size_t)MROWS * K2Q];     // 52 MB  x fp16x2, P8-perm
__device__ uint32_t g_wq [(size_t)K2Q * H3];        // 11.9MB w_qkv fp16x2 [k2][n]
__device__ uint32_t g_wo [(size_t)K2Q * HID];       // 4 MB   w_o fp16x2
__device__ uint32_t g_q  [(size_t)BH * SS * D2];    // 56.7MB Q fp16x2, perm, d-pad 0
__device__ uint32_t g_k  [(size_t)BH * SS * D2];    // 56.7MB K same
__device__ uint32_t g_v  [(size_t)BH * 96 * KV2];   // 63 MB  V^T fp16x2 [d][kv2], perm
__device__ uint32_t g_att[(size_t)MROWS * K2Q];     // 52 MB  att fp16x2, perm

// ---------------- helpers ----------------------------------------------------
__device__ __forceinline__ uint32_t smem_u32(const void* p) {
    return (uint32_t)__cvta_generic_to_shared(p);
}
__device__ __forceinline__ void cp_async16(uint32_t dst, const void* src) {
    asm volatile("cp.async.cg.shared.global [%0], [%1], 16;\n" :: "r"(dst), "l"(src));
}
__device__ __forceinline__ void cp_commit() {
    asm volatile("cp.async.commit_group;\n");
}
__device__ __forceinline__ uint32_t packh2(float lo, float hi) {
    __half2 h = __floats2half2_rn(lo, hi);   // .x = lo (low half)
    return *reinterpret_cast<uint32_t*>(&h);
}
__device__ __forceinline__ void mma_f16(float c[4], const uint32_t a[4], const uint32_t b[2]) {
    asm volatile(
        "mma.sync.aligned.m16n8k16.row.col.f32.f16.f16.f32 "
        "{%0,%1,%2,%3}, {%4,%5,%6,%7}, {%8,%9}, {%0,%1,%2,%3};\n"
        : "+f"(c[0]), "+f"(c[1]), "+f"(c[2]), "+f"(c[3])
        : "r"(a[0]), "r"(a[1]), "r"(a[2]), "r"(a[3]), "r"(b[0]), "r"(b[1]));
}
// position of k-pair t (0..7) inside its 8-block: (t4, t4+4) become adjacent
__device__ __forceinline__ int P8(int t) {
    return (t < 4) ? (2 * t) : (2 * (t - 4) + 1);
}

// ---------------- prep: w [K][N] fp32 -> [K/2][N] fp16x2 ---------------------
__global__ __launch_bounds__(256) void pack_weight(
    const float* __restrict__ w, uint32_t* __restrict__ wp, int K2, int N)
{
    int i = blockIdx.x * 256 + threadIdx.x;       // over K2 * N/4
    if (i >= K2 * (N / 4)) return;
    int k2 = i / (N / 4), n4 = (i % (N / 4)) * 4;
    float4 a = *(const float4*)(w + (size_t)(2 * k2) * N + n4);
    float4 b = *(const float4*)(w + (size_t)(2 * k2 + 1) * N + n4);
    uint4 o;
    o.x = packh2(a.x, b.x);
    o.y = packh2(a.y, b.y);
    o.z = packh2(a.z, b.z);
    o.w = packh2(a.w, b.w);
    *(uint4*)(wp + (size_t)k2 * N + n4) = o;
}

// ---------------- prep: x [M][1408] fp32 -> [M][704] fp16x2 P8-permuted ------
__global__ __launch_bounds__(256) void pack_x(
    const float* __restrict__ x, uint32_t* __restrict__ xp)
{
    long long i = (long long)blockIdx.x * 256 + threadIdx.x;  // row * 88 blocks
    if (i >= (long long)MROWS * 88) return;
    int row = (int)(i / 88), blk = (int)(i % 88);
    const float* src = x + (size_t)row * HID + blk * 16;
    float f[16];
#pragma unroll
    for (int t = 0; t < 4; t++) {
        float4 v = *(const float4*)(src + 4 * t);
        f[4*t] = v.x; f[4*t+1] = v.y; f[4*t+2] = v.z; f[4*t+3] = v.w;
    }
    uint32_t o[8];
#pragma unroll
    for (int t = 0; t < 8; t++)
        o[P8(t)] = packh2(f[2*t], f[2*t+1]);
    uint32_t* dst = xp + (size_t)row * K2Q + blk * 8;
    *(uint4*)dst       = make_uint4(o[0], o[1], o[2], o[3]);
    *(uint4*)(dst + 4) = make_uint4(o[4], o[5], o[6], o[7]);
}

// ---------------- fp16 tensor-core GEMM + bias -------------------------------
// C[M,N] = A@B + bias.  A: [M][K2] fp16x2 P8-perm. B: [K2][N] fp16x2 natural.
// BM=BN=128, BK=32 (16 k-pairs), 256 thr, 8 warps 64x32. N%128==0, K2%16==0.
__global__ __launch_bounds__(256, 2) void h16_gemm_bias(
    const uint32_t* __restrict__ Ap, const uint32_t* __restrict__ Bp,
    const float* __restrict__ bias, float* __restrict__ C,
    int M, int N, int K2)
{
    __shared__ uint32_t As[2][128][24];   // use [0..15]; stride 24 conflict-free
    __shared__ uint32_t Bs[2][16][136];   // stride 136 -> banks 8t4+g

    const int tid  = threadIdx.x;
    const int brow = blockIdx.y * 128;
    const int bcol = blockIdx.x * 128;
    const int wid  = tid >> 5;
    const int lane = tid & 31;
    const int g    = lane >> 2;
    const int t4   = lane & 3;
    const int wm   = (wid >> 2) * 64;
    const int wn   = (wid & 3) * 32;

    float acc[4][4][4];
#pragma unroll
    for (int mi = 0; mi < 4; mi++)
#pragma unroll
        for (int ni = 0; ni < 4; ni++)
#pragma unroll
            for (int r = 0; r < 4; r++) acc[mi][ni][r] = 0.f;

    const int nk = K2 / 16;

#define GLOADS(s, k0)                                                          \
    {                                                                          \
        _Pragma("unroll")                                                      \
        for (int t = 0; t < 2; t++) {                                          \
            int ch = tid + 256 * t;                                            \
            int arow = ch >> 2, ac = (ch & 3) * 4;                             \
            if (brow + arow < M)                                               \
                cp_async16(smem_u32(&As[s][arow][ac]),                         \
                           Ap + (size_t)(brow + arow) * K2 + (k0) + ac);       \
            else                                                               \
                *(uint4*)&As[s][arow][ac] = make_uint4(0, 0, 0, 0);            \
            int br = ch >> 5, bc = (ch & 31) * 4;                              \
            cp_async16(smem_u32(&Bs[s][br][bc]),                               \
                       Bp + (size_t)((k0) + br) * N + bcol + bc);              \
        }                                                                      \
        cp_commit();                                                           \
    }

    GLOADS(0, 0);

    for (int it = 0; it < nk; ++it) {
        const int s = it & 1;
        if (it + 1 < nk) {
            GLOADS((it + 1) & 1, (it + 1) * 16);
            asm volatile("cp.async.wait_group 1;\n");
        } else {
            asm volatile("cp.async.wait_group 0;\n");
        }
        __syncthreads();

#pragma unroll
        for (int kkl = 0; kkl < 2; kkl++) {
            uint32_t af[4][4], bf[4][2];
#pragma unroll
            for (int mi = 0; mi < 4; mi++) {
                int r0 = wm + mi * 16 + g;
                uint2 lo = *(const uint2*)&As[s][r0][8 * kkl + 2 * t4];
                uint2 hi = *(const uint2*)&As[s][r0 + 8][8 * kkl + 2 * t4];
                af[mi][0] = lo.x; af[mi][1] = hi.x;
                af[mi][2] = lo.y; af[mi][3] = hi.y;
            }
#pragma unroll
            for (int ni = 0; ni < 4; ni++) {
                int c0 = wn + ni * 8 + g;
                bf[ni][0] = Bs[s][8 * kkl + t4][c0];
                bf[ni][1] = Bs[s][8 * kkl + t4 + 4][c0];
            }
#pragma unroll
            for (int mi = 0; mi < 4; mi++)
#pragma unroll
                for (int ni = 0; ni < 4; ni++)
                    mma_f16(acc[mi][ni], af[mi], bf[ni]);
        }
        __syncthreads();
    }

#pragma unroll
    for (int mi = 0; mi < 4; mi++) {
#pragma unroll
        for (int ni = 0; ni < 4; ni++) {
            int r0 = brow + wm + mi * 16 + g;
            int c0 = bcol + wn + ni * 8 + t4 * 2;
            if (r0 < M) {
                C[(size_t)r0 * N + c0]     = acc[mi][ni][0] + bias[c0];
                C[(size_t)r0 * N + c0 + 1] = acc[mi][ni][1] + bias[c0 + 1];
            }
            if (r0 + 8 < M) {
                C[(size_t)(r0 + 8) * N + c0]     = acc[mi][ni][2] + bias[c0];
                C[(size_t)(r0 + 8) * N + c0 + 1] = acc[mi][ni][3] + bias[c0 + 1];
            }
        }
    }
#undef GLOADS
}

// ---------------- RoPE -> Qp, Kp fp16x2 [bh][s][48], P8-permuted d2 ----------
__global__ __launch_bounds__(256) void rope_scatter_qk(
    const float* __restrict__ qkv,
    uint32_t* __restrict__ Q, uint32_t* __restrict__ K)
{
    const long long idx = (long long)blockIdx.x * blockDim.x + threadIdx.x;
    const long long total = (long long)BB * SS * NH * (HD / 2);
    if (idx >= total) return;

    int j = (int)(idx % (HD / 2));            // d-pair 0..43
    int h = (int)((idx / (HD / 2)) % NH);
    int s = (int)((idx / ((HD / 2) * NH)) % SS);
    int b = (int)(idx / ((long long)(HD / 2) * NH * SS));

    float c, sn;
    if (s == SS - 1) {
        c = 1.f; sn = 0.f;
    } else {
        int fx = s % 24;
        int fy = s / 24;
        int jj = (j < 22) ? j : (j - 22);
        int coord = (j < 22) ? (fx + 1) : (fy + 1);
        float inv = expf(-(float)jj * 0.41865183508982657f); // ln(1e4)/22
        float arg = (float)coord * inv;
        c  = cosf(arg);
        sn = sinf(arg);
    }

    const float* base = qkv + (size_t)(b * SS + s) * H3 + h * HD;
    float q0 = base[2 * j],       q1 = base[2 * j + 1];
    float k0 = base[HID + 2 * j], k1 = base[HID + 2 * j + 1];

    size_t o = ((size_t)(b * NH + h) * SS + s) * D2 + (j & ~7) + P8(j & 7);
    Q[o] = packh2(q0 * c - q1 * sn, q0 * sn + q1 * c);
    K[o] = packh2(k0 * c - k1 * sn, k0 * sn + k1 * c);
}

// ---------------- V -> [bh][96][KV2] fp16x2 (kv-pairs), P8-perm kv2 ----------
__global__ __launch_bounds__(256) void v_transpose(
    const float* __restrict__ qkv, uint32_t* __restrict__ V)
{
    __shared__ float vt[64][89];

    const int bh = blockIdx.y;
    const int j0 = blockIdx.x * 64;
    const int b  = bh >> 4, h = bh & 15;
    const int tid = threadIdx.x;

    for (int idx = tid; idx < 64 * 22; idx += 256) {
        int row = idx / 22, c4 = (idx % 22) * 4;
        float4 v;
        if (j0 + row < SS)
            v = *(const float4*)(qkv + (size_t)(b * SS + j0 + row) * H3
                                 + 2 * HID + h * HD + c4);
        else
            v = make_float4(0.f, 0.f, 0.f, 0.f);
        vt[row][c4]     = v.x;
        vt[row][c4 + 1] = v.y;
        vt[row][c4 + 2] = v.z;
        vt[row][c4 + 3] = v.w;
    }
    __syncthreads();

    // output position c holds kv2 = invP8(c) within each 8-block
    for (int idx = tid; idx < HD * 32; idx += 256) {
        int d = idx >> 5, c = idx & 31;
        int p = c & 7;
        int kv2l = (c & ~7) + ((c & 1) ? ((p >> 1) + 4) : (p >> 1));
        V[((size_t)bh * 96 + d) * KV2 + (j0 >> 1) + c] =
            packh2(vt[2 * kv2l][d], vt[2 * kv2l + 1][d]);
    }
}

// ---------------- fused flash attention (fp16 mma) ---------------------------
// Block = (q-tile 128, bh). 8 warps x 16 rows. K/V fp16 tiles double-buffered.
__global__ __launch_bounds__(256, 2) void flash_attn(
    const uint32_t* __restrict__ Q, const uint32_t* __restrict__ K,
    const uint32_t* __restrict__ V, uint32_t* __restrict__ O)
{
    extern __shared__ uint32_t smu[];
    uint32_t (*Ks)[64][56] = (uint32_t (*)[64][56])smu;               // 2 stages
    uint32_t (*Vs)[96][40] = (uint32_t (*)[96][40])(smu + 2 * 64 * 56);

    const int bh  = blockIdx.y;
    const int q0  = blockIdx.x * 128;
    const int tid = threadIdx.x;
    const int wid = tid >> 5;
    const int lane = tid & 31;
    const int g   = lane >> 2;
    const int t4  = lane & 3;

    const uint32_t* Qb = Q + (size_t)bh * SS * D2;
    const uint32_t* Kb = K + (size_t)bh * SS * D2;
    const uint32_t* Vb = V + (size_t)bh * 96 * KV2;

    // preload Q fragments: 6 kk chunks x 4 regs
    const int r0 = q0 + wid * 16 + g;
    const int r1 = r0 + 8;
    const int r0c = (r0 < SS) ? r0 : (SS - 1);
    const int r1c = (r1 < SS) ? r1 : (SS - 1);
    uint32_t qf[6][4];
#pragma unroll
    for (int kk = 0; kk < 6; kk++) {
        uint2 lo = *(const uint2*)(Qb + (size_t)r0c * D2 + 8 * kk + 2 * t4);
        uint2 hi = *(const uint2*)(Qb + (size_t)r1c * D2 + 8 * kk + 2 * t4);
        qf[kk][0] = lo.x; qf[kk][1] = hi.x;
        qf[kk][2] = lo.y; qf[kk][3] = hi.y;
    }

    float oacc[11][4];
#pragma unroll
    for (int ni = 0; ni < 11; ni++)
#pragma unroll
        for (int r = 0; r < 4; r++) oacc[ni][r] = 0.f;
    float m0 = -1e30f, m1 = -1e30f, l0 = 0.f, l1 = 0.f;

#define LOAD_TILE(s, j0v)                                                  \
    {                                                                      \
        for (int idx = tid; idx < 64 * 12; idx += 256) {                   \
            int row = idx / 12, c = (idx % 12) * 4;                        \
            int jr = (j0v) + row; jr = (jr < SS) ? jr : (SS - 1);          \
            cp_async16(smem_u32(&Ks[s][row][c]), Kb + (size_t)jr * D2 + c);\
        }                                                                  \
        for (int idx = tid; idx < 96 * 8; idx += 256) {                    \
            int d = idx >> 3, c = (idx & 7) * 4;                           \
            cp_async16(smem_u32(&Vs[s][d][c]),                             \
                       Vb + (size_t)d * KV2 + ((j0v) >> 1) + c);           \
        }                                                                  \
        cp_commit();                                                       \
    }

    LOAD_TILE(0, 0);

    for (int it = 0; it < NT; ++it) {
        const int s = it & 1;
        const int j0 = it * 64;
        if (it + 1 < NT) {
            LOAD_TILE((it + 1) & 1, (it + 1) * 64);
            asm volatile("cp.async.wait_group 1;\n");
        } else {
            asm volatile("cp.async.wait_group 0;\n");
        }
        __syncthreads();

        // ---- S = Q K^T (16 x 64 per warp) ----
        float sacc[8][4];
#pragma unroll
        for (int ni = 0; ni < 8; ni++)
#pragma unroll
            for (int r = 0; r < 4; r++) sacc[ni][r] = 0.f;

#pragma unroll
        for (int kk = 0; kk < 6; kk++) {
#pragma unroll
            for (int ni = 0; ni < 8; ni++) {
                uint2 kb = *(const uint2*)&Ks[s][ni * 8 + g][8 * kk + 2 * t4];
                uint32_t bf[2] = {kb.x, kb.y};
                mma_f16(sacc[ni], qf[kk], bf);
            }
        }

        // ---- scale + mask ----
#pragma unroll
        for (int ni = 0; ni < 8; ni++)
#pragma unroll
            for (int r = 0; r < 4; r++) sacc[ni][r] *= SCALEF;

        if (j0 + 64 > SS) {
#pragma unroll
            for (int ni = 0; ni < 8; ni++) {
                int c = j0 + ni * 8 + 2 * t4;
                if (c     >= SS) { sacc[ni][0] = -1e30f; sacc[ni][2] = -1e30f; }
                if (c + 1 >= SS) { sacc[ni][1] = -1e30f; sacc[ni][3] = -1e30f; }
            }
        }

        // ---- online softmax (quad-local rows) ----
        float mx0 = -1e30f, mx1 = -1e30f;
#pragma unroll
        for (int ni = 0; ni < 8; ni++) {
            mx0 = fmaxf(mx0, fmaxf(sacc[ni][0], sacc[ni][1]));
            mx1 = fmaxf(mx1, fmaxf(sacc[ni][2], sacc[ni][3]));
        }
#pragma unroll
        for (int off = 1; off < 4; off <<= 1) {
            mx0 = fmaxf(mx0, __shfl_xor_sync(0xffffffffu, mx0, off));
            mx1 = fmaxf(mx1, __shfl_xor_sync(0xffffffffu, mx1, off));
        }

        float m0n = fmaxf(m0, mx0);
        float m1n = fmaxf(m1, mx1);
        float a0 = __expf(m0 - m0n);
        float a1 = __expf(m1 - m1n);

        float rs0 = 0.f, rs1 = 0.f;
#pragma unroll
        for (int ni = 0; ni < 8; ni++) {
            sacc[ni][0] = __expf(sacc[ni][0] - m0n);
            sacc[ni][1] = __expf(sacc[ni][1] - m0n);
            sacc[ni][2] = __expf(sacc[ni][2] - m1n);
            sacc[ni][3] = __expf(sacc[ni][3] - m1n);
            rs0 += sacc[ni][0] + sacc[ni][1];
            rs1 += sacc[ni][2] + sacc[ni][3];
        }
#pragma unroll
        for (int off = 1; off < 4; off <<= 1) {
            rs0 += __shfl_xor_sync(0xffffffffu, rs0, off);
            rs1 += __shfl_xor_sync(0xffffffffu, rs1, off);
        }
        l0 = l0 * a0 + rs0;
        l1 = l1 * a1 + rs1;
        m0 = m0n;
        m1 = m1n;

#pragma unroll
        for (int ni = 0; ni < 11; ni++) {
            oacc[ni][0] *= a0;
            oacc[ni][1] *= a0;
            oacc[ni][2] *= a1;
            oacc[ni][3] *= a1;
        }

        // ---- O += P V : fp16 C-layout == A-layout (no shuffle!) ----
#pragma unroll
        for (int kk = 0; kk < 4; kk++) {
            uint32_t af[4];
            af[0] = packh2(sacc[2*kk][0],   sacc[2*kk][1]);     // row g,   kv 16kk+2t4..
            af[1] = packh2(sacc[2*kk][2],   sacc[2*kk][3]);     // row g+8
            af[2] = packh2(sacc[2*kk+1][0], sacc[2*kk+1][1]);   // row g,   kv +8
            af[3] = packh2(sacc[2*kk+1][2], sacc[2*kk+1][3]);   // row g+8
#pragma unroll
            for (int ni = 0; ni < 11; ni++) {
                uint2 vb = *(const uint2*)&Vs[s][ni * 8 + g][8 * kk + 2 * t4];
                uint32_t bf[2] = {vb.x, vb.y};
                mma_f16(oacc[ni], af, bf);
            }
        }
        __syncthreads();
    }

    // ---- normalize + store packed fp16x2 in o-proj A layout ----
    const int b = bh >> 4, h = bh & 15;
    const float il0 = 1.f / l0;
    const float il1 = 1.f / l1;
    if (r0 < SS) {
        uint32_t* o = O + (size_t)(b * SS + r0) * K2Q;
#pragma unroll
        for (int ni = 0; ni < 11; ni++) {
            int d2 = h * 44 + ni * 4 + t4;
            o[(d2 & ~7) + P8(d2 & 7)] =
                packh2(oacc[ni][0] * il0, oacc[ni][1] * il0);
        }
    }
    if (r1 < SS) {
        uint32_t* o = O + (size_t)(b * SS + r1) * K2Q;
#pragma unroll
        for (int ni = 0; ni < 11; ni++) {
            int d2 = h * 44 + ni * 4 + t4;
            o[(d2 & ~7) + P8(d2 & 7)] =
                packh2(oacc[ni][2] * il1, oacc[ni][3] * il1);
        }
    }
#undef LOAD_TILE
}

// ---------------- launch -----------------------------------------------------
extern "C" void kernel_launch(void* const* d_in, const int* in_sizes, int n_in,
                              void* d_out, int out_size)
{
    const float* x     = (const float*)d_in[0];
    const float* w_qkv = (const float*)d_in[1];
    const float* b_qkv = (const float*)d_in[2];
    const float* w_o   = (const float*)d_in[3];
    const float* b_o   = (const float*)d_in[4];
    float* out = (float*)d_out;

    float *qkv;
    uint32_t *xr, *wq, *wo, *q, *k, *v, *att;
    cudaGetSymbolAddress((void**)&qkv, g_qkv);
    cudaGetSymbolAddress((void**)&xr,  g_xr);
    cudaGetSymbolAddress((void**)&wq,  g_wq);
    cudaGetSymbolAddress((void**)&wo,  g_wo);
    cudaGetSymbolAddress((void**)&q,   g_q);
    cudaGetSymbolAddress((void**)&k,   g_k);
    cudaGetSymbolAddress((void**)&v,   g_v);
    cudaGetSymbolAddress((void**)&att, g_att);

    // 0) prep: pack weights + x to fp16x2 layouts
    {
        int n = K2Q * (H3 / 4);
        pack_weight<<<(n + 255) / 256, 256>>>(w_qkv, wq, K2Q, H3);
        n = K2Q * (HID / 4);
        pack_weight<<<(n + 255) / 256, 256>>>(w_o, wo, K2Q, HID);
        long long nb = (long long)MROWS * 88;
        pack_x<<<(int)((nb + 255) / 256), 256>>>(x, xr);
    }

    // 1) QKV projection (fp16 tensor cores, fp32 accum + bias)
    h16_gemm_bias<<<dim3(H3 / 128, (MROWS + 127) / 128), 256>>>(
        xr, wq, b_qkv, qkv, MROWS, H3, K2Q);

    // 2) RoPE Q,K (fp16, permuted) + V transpose (fp16, [d][kv2])
    {
        long long total = (long long)BB * SS * NH * (HD / 2);
        rope_scatter_qk<<<(int)((total + 255) / 256), 256>>>(qkv, q, k);
        v_transpose<<<dim3(NT, BH), 256>>>(qkv, v);
    }

    // 3) fused flash attention -> att (fp16x2, o-proj A layout)
    {
        const int smem_bytes = (2 * 64 * 56 + 2 * 96 * 40) * 4;  // 59392
        cudaFuncSetAttribute(flash_attn,
                             cudaFuncAttributeMaxDynamicSharedMemorySize,
                             smem_bytes);
        flash_attn<<<dim3((SS + 127) / 128, BH), 256, smem_bytes>>>(q, k, v, att);
    }

    // 4) output projection (fp16 tensor cores)
    h16_gemm_bias<<<dim3(HID / 128, (MROWS + 127) / 128), 256>>>(
        att, wo, b_o, out, MROWS, HID, K2Q);
}

// round 7
// speedup vs baseline: 2.3883x; 1.0846x over previous
#include <cuda_runtime.h>
#include <cuda_fp16.h>
#include <math.h>
#include <stdint.h>

#define BB     32
#define SS     577
#define HID    1408
#define H3     4224
#define NH     16
#define HD     88
#define BH     (BB*NH)      // 512
#define MROWS  (BB*SS)      // 18464
#define K2Q    (HID/2)      // 704
#define D2     48           // padded per-head d-pairs
#define SPAD   640
#define KV2    (SPAD/2)     // 320
#define NT     10
#define SCALEF 0.10660035817780521f   // 88^-0.5

// ---------------- scratch (static device globals) ----------------------------
__device__ __align__(16) __half g_qkvh[(size_t)MROWS * H3];   // 156 MB fp16
__device__ __align__(16) __half g_xh [(size_t)MROWS * HID];   // 52 MB  x fp16
__device__ __align__(16) __half g_wqt[(size_t)H3 * HID];      // w_qkv^T fp16 [n][k]
__device__ __align__(16) __half g_wot[(size_t)HID * HID];     // w_o^T fp16
__device__ uint32_t g_q  [(size_t)BH * SS * D2];    // Q fp16x2, P8-perm (flash)
__device__ uint32_t g_k  [(size_t)BH * SS * D2];
__device__ uint32_t g_v  [(size_t)BH * 96 * KV2];
__device__ __align__(16) uint32_t g_att[(size_t)MROWS * K2Q]; // att fp16 plain K-major

// ---------------- helpers ----------------------------------------------------
__device__ __forceinline__ uint32_t smem_u32(const void* p) {
    return (uint32_t)__cvta_generic_to_shared(p);
}
__device__ __forceinline__ void cp_async16(uint32_t dst, const void* src) {
    asm volatile("cp.async.cg.shared.global [%0], [%1], 16;\n" :: "r"(dst), "l"(src));
}
__device__ __forceinline__ void cp_commit() {
    asm volatile("cp.async.commit_group;\n");
}
__device__ __forceinline__ uint32_t packh2(float lo, float hi) {
    __half2 h = __floats2half2_rn(lo, hi);
    return *reinterpret_cast<uint32_t*>(&h);
}
__device__ __forceinline__ void mma_f16(float c[4], const uint32_t a[4], const uint32_t b[2]) {
    asm volatile(
        "mma.sync.aligned.m16n8k16.row.col.f32.f16.f16.f32 "
        "{%0,%1,%2,%3}, {%4,%5,%6,%7}, {%8,%9}, {%0,%1,%2,%3};\n"
        : "+f"(c[0]), "+f"(c[1]), "+f"(c[2]), "+f"(c[3])
        : "r"(a[0]), "r"(a[1]), "r"(a[2]), "r"(a[3]), "r"(b[0]), "r"(b[1]));
}
#define LDSM4(r0, r1, r2, r3, addr)                                             \
    asm volatile("ldmatrix.sync.aligned.m8n8.x4.shared.b16 {%0,%1,%2,%3}, [%4];" \
                 : "=r"(r0), "=r"(r1), "=r"(r2), "=r"(r3) : "r"(addr))
__device__ __forceinline__ int P8(int t) {
    return (t < 4) ? (2 * t) : (2 * (t - 4) + 1);
}

// ---------------- prep: x fp32 -> fp16 plain ---------------------------------
__global__ __launch_bounds__(256) void pack_xh(
    const float* __restrict__ x, __half* __restrict__ xh, long long n8)
{
    long long i = (long long)blockIdx.x * 256 + threadIdx.x;
    if (i >= n8) return;
    float4 a = ((const float4*)x)[2 * i];
    float4 b = ((const float4*)x)[2 * i + 1];
    uint4 o;
    o.x = packh2(a.x, a.y); o.y = packh2(a.z, a.w);
    o.z = packh2(b.x, b.y); o.w = packh2(b.z, b.w);
    ((uint4*)xh)[i] = o;
}

// ---------------- prep: w [K][N] fp32 -> wt [N][K] fp16 ----------------------
__global__ __launch_bounds__(256) void transpose_pack(
    const float* __restrict__ w, __half* __restrict__ wt, int K, int N)
{
    __shared__ float t[32][33];
    const int n0 = blockIdx.x * 32;
    const int k0 = blockIdx.y * 32;
    const int tx = threadIdx.x & 31;
    const int ty = threadIdx.x >> 5;
    for (int i = ty; i < 32; i += 8)
        t[i][tx] = w[(size_t)(k0 + i) * N + n0 + tx];
    __syncthreads();
    for (int i = ty; i < 32; i += 8)
        wt[(size_t)(n0 + i) * K + k0 + tx] = __float2half_rn(t[tx][i]);
}

// ---------------- fp16 GEMM + bias, ldmatrix fragments -----------------------
// C[M,N] = A[M,K] @ Bt[N,K]^T + bias. BM=BN=128, BK=64 halves, 2 stages.
// smem rows: 64 halves data padded to 144B (LDSM conflict-free: (9r+c) mod 8).
#define ROWB   144
#define HSTAGE 36864     // A 128*144 + B 128*144

__global__ __launch_bounds__(256, 2) void h16_gemm_ldsm(
    const __half* __restrict__ A, const __half* __restrict__ Bt,
    const float* __restrict__ bias, void* __restrict__ Cout,
    int M, int N, int K, int out_half)
{
    extern __shared__ __align__(16) char gsm[];
    __shared__ float sbias[128];

    const int tid  = threadIdx.x;
    const int brow = blockIdx.y * 128;
    const int bcol = blockIdx.x * 128;
    const int wid  = tid >> 5;
    const int lane = tid & 31;
    const int g    = lane >> 2;
    const int t4   = lane & 3;
    const int wm   = (wid >> 2) * 64;
    const int wn   = (wid & 3) * 32;

    if (tid < 128) sbias[tid] = bias[bcol + tid];

    const uint32_t sb = smem_u32(gsm);
    // lane-invariant pieces of LDSM addresses
    const uint32_t a_off = (uint32_t)(wm + (lane & 15)) * ROWB + ((lane >> 4) << 4);
    const uint32_t b_off = (uint32_t)(wn + (lane & 7) + ((lane >> 4) << 3)) * ROWB
                           + (((lane >> 3) & 1) << 4);

    float acc[4][4][4];
#pragma unroll
    for (int mi = 0; mi < 4; mi++)
#pragma unroll
        for (int ni = 0; ni < 4; ni++)
#pragma unroll
            for (int r = 0; r < 4; r++) acc[mi][ni][r] = 0.f;

    const int nk = K / 64;

#define GLOADS(s, c)                                                           \
    {                                                                          \
        const uint32_t sA = sb + (s) * HSTAGE;                                 \
        const uint32_t sB = sA + 128 * ROWB;                                   \
        const int kc = (c) * 64;                                               \
        _Pragma("unroll")                                                      \
        for (int t = 0; t < 4; t++) {                                          \
            int idx = tid + 256 * t;                                           \
            int row = idx >> 3, cc = idx & 7;                                  \
            int ra = brow + row; if (ra >= M) ra = M - 1;                      \
            cp_async16(sA + row * ROWB + cc * 16,                              \
                       A + (size_t)ra * K + kc + cc * 8);                      \
            cp_async16(sB + row * ROWB + cc * 16,                              \
                       Bt + (size_t)(bcol + row) * K + kc + cc * 8);           \
        }                                                                      \
        cp_commit();                                                           \
    }

    GLOADS(0, 0);

    for (int it = 0; it < nk; ++it) {
        const int s = it & 1;
        if (it + 1 < nk) {
            GLOADS((it + 1) & 1, it + 1);
            asm volatile("cp.async.wait_group 1;\n" ::: "memory");
        } else {
            asm volatile("cp.async.wait_group 0;\n" ::: "memory");
        }
        __syncthreads();

        const uint32_t sA = sb + s * HSTAGE;
        const uint32_t sB = sA + 128 * ROWB;
#pragma unroll
        for (int kkl = 0; kkl < 4; kkl++) {
            uint32_t af[4][4], bf[2][4];
#pragma unroll
            for (int mi = 0; mi < 4; mi++)
                LDSM4(af[mi][0], af[mi][1], af[mi][2], af[mi][3],
                      sA + a_off + mi * (16 * ROWB) + kkl * 32);
#pragma unroll
            for (int nj = 0; nj < 2; nj++)
                LDSM4(bf[nj][0], bf[nj][1], bf[nj][2], bf[nj][3],
                      sB + b_off + nj * (16 * ROWB) + kkl * 32);
#pragma unroll
            for (int mi = 0; mi < 4; mi++)
#pragma unroll
                for (int ni = 0; ni < 4; ni++) {
                    uint32_t bb[2] = {bf[ni >> 1][(ni & 1) * 2],
                                      bf[ni >> 1][(ni & 1) * 2 + 1]};
                    mma_f16(acc[mi][ni], af[mi], bb);
                }
        }
        __syncthreads();
    }

    if (out_half) {
        __half* C = (__half*)Cout;
#pragma unroll
        for (int mi = 0; mi < 4; mi++)
#pragma unroll
            for (int ni = 0; ni < 4; ni++) {
                int r0 = brow + wm + mi * 16 + g;
                int c0 = bcol + wn + ni * 8 + t4 * 2;
                float bx = sbias[wn + ni * 8 + t4 * 2];
                float by = sbias[wn + ni * 8 + t4 * 2 + 1];
                if (r0 < M)
                    *(__half2*)(C + (size_t)r0 * N + c0) =
                        __floats2half2_rn(acc[mi][ni][0] + bx, acc[mi][ni][1] + by);
                if (r0 + 8 < M)
                    *(__half2*)(C + (size_t)(r0 + 8) * N + c0) =
                        __floats2half2_rn(acc[mi][ni][2] + bx, acc[mi][ni][3] + by);
            }
    } else {
        float* C = (float*)Cout;
#pragma unroll
        for (int mi = 0; mi < 4; mi++)
#pragma unroll
            for (int ni = 0; ni < 4; ni++) {
                int r0 = brow + wm + mi * 16 + g;
                int c0 = bcol + wn + ni * 8 + t4 * 2;
                float bx = sbias[wn + ni * 8 + t4 * 2];
                float by = sbias[wn + ni * 8 + t4 * 2 + 1];
                if (r0 < M) {
                    C[(size_t)r0 * N + c0]     = acc[mi][ni][0] + bx;
                    C[(size_t)r0 * N + c0 + 1] = acc[mi][ni][1] + by;
                }
                if (r0 + 8 < M) {
                    C[(size_t)(r0 + 8) * N + c0]     = acc[mi][ni][2] + bx;
                    C[(size_t)(r0 + 8) * N + c0 + 1] = acc[mi][ni][3] + by;
                }
            }
    }
#undef GLOADS
}

// ---------------- RoPE -> Qp, Kp fp16x2 [bh][s][48], P8-permuted -------------
__global__ __launch_bounds__(256) void rope_scatter_qk(
    const __half* __restrict__ qkv,
    uint32_t* __restrict__ Q, uint32_t* __restrict__ K)
{
    const long long idx = (long long)blockIdx.x * blockDim.x + threadIdx.x;
    const long long total = (long long)BB * SS * NH * (HD / 2);
    if (idx >= total) return;

    int j = (int)(idx % (HD / 2));
    int h = (int)((idx / (HD / 2)) % NH);
    int s = (int)((idx / ((HD / 2) * NH)) % SS);
    int b = (int)(idx / ((long long)(HD / 2) * NH * SS));

    float c, sn;
    if (s == SS - 1) {
        c = 1.f; sn = 0.f;
    } else {
        int fx = s % 24;
        int fy = s / 24;
        int jj = (j < 22) ? j : (j - 22);
        int coord = (j < 22) ? (fx + 1) : (fy + 1);
        float inv = expf(-(float)jj * 0.41865183508982657f); // ln(1e4)/22
        float arg = (float)coord * inv;
        c  = cosf(arg);
        sn = sinf(arg);
    }

    const __half* base = qkv + (size_t)(b * SS + s) * H3 + h * HD;
    float2 qp = __half22float2(*(const __half2*)(base + 2 * j));
    float2 kp = __half22float2(*(const __half2*)(base + HID + 2 * j));

    size_t o = ((size_t)(b * NH + h) * SS + s) * D2 + (j & ~7) + P8(j & 7);
    Q[o] = packh2(qp.x * c - qp.y * sn, qp.x * sn + qp.y * c);
    K[o] = packh2(kp.x * c - kp.y * sn, kp.x * sn + kp.y * c);
}

// ---------------- V -> [bh][96][KV2] fp16x2 (kv-pairs), P8-perm --------------
__global__ __launch_bounds__(256) void v_transpose(
    const __half* __restrict__ qkv, uint32_t* __restrict__ V)
{
    __shared__ float vt[64][89];

    const int bh = blockIdx.y;
    const int j0 = blockIdx.x * 64;
    const int b  = bh >> 4, h = bh & 15;
    const int tid = threadIdx.x;

    for (int idx = tid; idx < 64 * 22; idx += 256) {
        int row = idx / 22, c4 = (idx % 22) * 4;
        float2 v01 = make_float2(0.f, 0.f), v23 = make_float2(0.f, 0.f);
        if (j0 + row < SS) {
            const __half* src = qkv + (size_t)(b * SS + j0 + row) * H3
                                + 2 * HID + h * HD + c4;
            uint2 u = *(const uint2*)src;
            v01 = __half22float2(*reinterpret_cast<__half2*>(&u.x));
            v23 = __half22float2(*reinterpret_cast<__half2*>(&u.y));
        }
        vt[row][c4]     = v01.x;
        vt[row][c4 + 1] = v01.y;
        vt[row][c4 + 2] = v23.x;
        vt[row][c4 + 3] = v23.y;
    }
    __syncthreads();

    for (int idx = tid; idx < HD * 32; idx += 256) {
        int d = idx >> 5, c = idx & 31;
        int p = c & 7;
        int kv2l = (c & ~7) + ((c & 1) ? ((p >> 1) + 4) : (p >> 1));
        V[((size_t)bh * 96 + d) * KV2 + (j0 >> 1) + c] =
            packh2(vt[2 * kv2l][d], vt[2 * kv2l + 1][d]);
    }
}

// ---------------- fused flash attention (fp16 mma) ---------------------------
__global__ __launch_bounds__(256, 2) void flash_attn(
    const uint32_t* __restrict__ Q, const uint32_t* __restrict__ K,
    const uint32_t* __restrict__ V, uint32_t* __restrict__ O)
{
    extern __shared__ uint32_t smu[];
    uint32_t (*Ks)[64][56] = (uint32_t (*)[64][56])smu;
    uint32_t (*Vs)[96][40] = (uint32_t (*)[96][40])(smu + 2 * 64 * 56);

    const int bh  = blockIdx.y;
    const int q0  = blockIdx.x * 128;
    const int tid = threadIdx.x;
    const int wid = tid >> 5;
    const int lane = tid & 31;
    const int g   = lane >> 2;
    const int t4  = lane & 3;

    const uint32_t* Qb = Q + (size_t)bh * SS * D2;
    const uint32_t* Kb = K + (size_t)bh * SS * D2;
    const uint32_t* Vb = V + (size_t)bh * 96 * KV2;

    const int r0 = q0 + wid * 16 + g;
    const int r1 = r0 + 8;
    const int r0c = (r0 < SS) ? r0 : (SS - 1);
    const int r1c = (r1 < SS) ? r1 : (SS - 1);
    uint32_t qf[6][4];
#pragma unroll
    for (int kk = 0; kk < 6; kk++) {
        uint2 lo = *(const uint2*)(Qb + (size_t)r0c * D2 + 8 * kk + 2 * t4);
        uint2 hi = *(const uint2*)(Qb + (size_t)r1c * D2 + 8 * kk + 2 * t4);
        qf[kk][0] = lo.x; qf[kk][1] = hi.x;
        qf[kk][2] = lo.y; qf[kk][3] = hi.y;
    }

    float oacc[11][4];
#pragma unroll
    for (int ni = 0; ni < 11; ni++)
#pragma unroll
        for (int r = 0; r < 4; r++) oacc[ni][r] = 0.f;
    float m0 = -1e30f, m1 = -1e30f, l0 = 0.f, l1 = 0.f;

#define LOAD_TILE(s, j0v)                                                  \
    {                                                                      \
        for (int idx = tid; idx < 64 * 12; idx += 256) {                   \
            int row = idx / 12, c = (idx % 12) * 4;                        \
            int jr = (j0v) + row; jr = (jr < SS) ? jr : (SS - 1);          \
            cp_async16(smem_u32(&Ks[s][row][c]), Kb + (size_t)jr * D2 + c);\
        }                                                                  \
        for (int idx = tid; idx < 96 * 8; idx += 256) {                    \
            int d = idx >> 3, c = (idx & 7) * 4;                           \
            cp_async16(smem_u32(&Vs[s][d][c]),                             \
                       Vb + (size_t)d * KV2 + ((j0v) >> 1) + c);           \
        }                                                                  \
        cp_commit();                                                       \
    }

    LOAD_TILE(0, 0);

    for (int it = 0; it < NT; ++it) {
        const int s = it & 1;
        const int j0 = it * 64;
        if (it + 1 < NT) {
            LOAD_TILE((it + 1) & 1, (it + 1) * 64);
            asm volatile("cp.async.wait_group 1;\n");
        } else {
            asm volatile("cp.async.wait_group 0;\n");
        }
        __syncthreads();

        float sacc[8][4];
#pragma unroll
        for (int ni = 0; ni < 8; ni++)
#pragma unroll
            for (int r = 0; r < 4; r++) sacc[ni][r] = 0.f;

#pragma unroll
        for (int kk = 0; kk < 6; kk++) {
#pragma unroll
            for (int ni = 0; ni < 8; ni++) {
                uint2 kb = *(const uint2*)&Ks[s][ni * 8 + g][8 * kk + 2 * t4];
                uint32_t bf[2] = {kb.x, kb.y};
                mma_f16(sacc[ni], qf[kk], bf);
            }
        }

#pragma unroll
        for (int ni = 0; ni < 8; ni++)
#pragma unroll
            for (int r = 0; r < 4; r++) sacc[ni][r] *= SCALEF;

        if (j0 + 64 > SS) {
#pragma unroll
            for (int ni = 0; ni < 8; ni++) {
                int c = j0 + ni * 8 + 2 * t4;
                if (c     >= SS) { sacc[ni][0] = -1e30f; sacc[ni][2] = -1e30f; }
                if (c + 1 >= SS) { sacc[ni][1] = -1e30f; sacc[ni][3] = -1e30f; }
            }
        }

        float mx0 = -1e30f, mx1 = -1e30f;
#pragma unroll
        for (int ni = 0; ni < 8; ni++) {
            mx0 = fmaxf(mx0, fmaxf(sacc[ni][0], sacc[ni][1]));
            mx1 = fmaxf(mx1, fmaxf(sacc[ni][2], sacc[ni][3]));
        }
#pragma unroll
        for (int off = 1; off < 4; off <<= 1) {
            mx0 = fmaxf(mx0, __shfl_xor_sync(0xffffffffu, mx0, off));
            mx1 = fmaxf(mx1, __shfl_xor_sync(0xffffffffu, mx1, off));
        }

        float m0n = fmaxf(m0, mx0);
        float m1n = fmaxf(m1, mx1);
        float a0 = __expf(m0 - m0n);
        float a1 = __expf(m1 - m1n);

        float rs0 = 0.f, rs1 = 0.f;
#pragma unroll
        for (int ni = 0; ni < 8; ni++) {
            sacc[ni][0] = __expf(sacc[ni][0] - m0n);
            sacc[ni][1] = __expf(sacc[ni][1] - m0n);
            sacc[ni][2] = __expf(sacc[ni][2] - m1n);
            sacc[ni][3] = __expf(sacc[ni][3] - m1n);
            rs0 += sacc[ni][0] + sacc[ni][1];
            rs1 += sacc[ni][2] + sacc[ni][3];
        }
#pragma unroll
        for (int off = 1; off < 4; off <<= 1) {
            rs0 += __shfl_xor_sync(0xffffffffu, rs0, off);
            rs1 += __shfl_xor_sync(0xffffffffu, rs1, off);
        }
        l0 = l0 * a0 + rs0;
        l1 = l1 * a1 + rs1;
        m0 = m0n;
        m1 = m1n;

#pragma unroll
        for (int ni = 0; ni < 11; ni++) {
            oacc[ni][0] *= a0;
            oacc[ni][1] *= a0;
            oacc[ni][2] *= a1;
            oacc[ni][3] *= a1;
        }

#pragma unroll
        for (int kk = 0; kk < 4; kk++) {
            uint32_t af[4];
            af[0] = packh2(sacc[2*kk][0],   sacc[2*kk][1]);
            af[1] = packh2(sacc[2*kk][2],   sacc[2*kk][3]);
            af[2] = packh2(sacc[2*kk+1][0], sacc[2*kk+1][1]);
            af[3] = packh2(sacc[2*kk+1][2], sacc[2*kk+1][3]);
#pragma unroll
            for (int ni = 0; ni < 11; ni++) {
                uint2 vb = *(const uint2*)&Vs[s][ni * 8 + g][8 * kk + 2 * t4];
                uint32_t bf[2] = {vb.x, vb.y};
                mma_f16(oacc[ni], af, bf);
            }
        }
        __syncthreads();
    }

    // store plain K-major fp16 pairs (gemm A layout)
    const float il0 = 1.f / l0;
    const float il1 = 1.f / l1;
    const int b = bh >> 4, h = bh & 15;
    if (r0 < SS) {
        uint32_t* o = O + (size_t)(b * SS + r0) * K2Q;
#pragma unroll
        for (int ni = 0; ni < 11; ni++)
            o[h * 44 + ni * 4 + t4] = packh2(oacc[ni][0] * il0, oacc[ni][1] * il0);
    }
    if (r1 < SS) {
        uint32_t* o = O + (size_t)(b * SS + r1) * K2Q;
#pragma unroll
        for (int ni = 0; ni < 11; ni++)
            o[h * 44 + ni * 4 + t4] = packh2(oacc[ni][2] * il1, oacc[ni][3] * il1);
    }
#undef LOAD_TILE
}

// ---------------- launch -----------------------------------------------------
extern "C" void kernel_launch(void* const* d_in, const int* in_sizes, int n_in,
                              void* d_out, int out_size)
{
    const float* x     = (const float*)d_in[0];
    const float* w_qkv = (const float*)d_in[1];
    const float* b_qkv = (const float*)d_in[2];
    const float* w_o   = (const float*)d_in[3];
    const float* b_o   = (const float*)d_in[4];
    float* out = (float*)d_out;

    __half *qkvh, *xh, *wqt, *wot;
    uint32_t *q, *k, *v, *att;
    cudaGetSymbolAddress((void**)&qkvh, g_qkvh);
    cudaGetSymbolAddress((void**)&xh,   g_xh);
    cudaGetSymbolAddress((void**)&wqt,  g_wqt);
    cudaGetSymbolAddress((void**)&wot,  g_wot);
    cudaGetSymbolAddress((void**)&q,    g_q);
    cudaGetSymbolAddress((void**)&k,    g_k);
    cudaGetSymbolAddress((void**)&v,    g_v);
    cudaGetSymbolAddress((void**)&att,  g_att);

    const int gemm_smem = 2 * HSTAGE;   // 73728
    cudaFuncSetAttribute(h16_gemm_ldsm,
                         cudaFuncAttributeMaxDynamicSharedMemorySize, gemm_smem);

    // 0) prep: x -> fp16; weights -> transposed fp16
    {
        long long n8 = (long long)MROWS * HID / 8;
        pack_xh<<<(int)((n8 + 255) / 256), 256>>>(x, xh, n8);
        transpose_pack<<<dim3(H3 / 32, HID / 32), 256>>>(w_qkv, wqt, HID, H3);
        transpose_pack<<<dim3(HID / 32, HID / 32), 256>>>(w_o, wot, HID, HID);
    }

    // 1) QKV projection -> fp16 qkv
    h16_gemm_ldsm<<<dim3(H3 / 128, (MROWS + 127) / 128), 256, gemm_smem>>>(
        xh, wqt, b_qkv, qkvh, MROWS, H3, HID, 1);

    // 2) RoPE Q,K + V transpose (fp16 flash layouts)
    {
        long long total = (long long)BB * SS * NH * (HD / 2);
        rope_scatter_qk<<<(int)((total + 255) / 256), 256>>>(qkvh, q, k);
        v_transpose<<<dim3(NT, BH), 256>>>(qkvh, v);
    }

    // 3) fused flash attention -> att (fp16 plain K-major)
    {
        const int smem_bytes = (2 * 64 * 56 + 2 * 96 * 40) * 4;  // 59392
        cudaFuncSetAttribute(flash_attn,
                             cudaFuncAttributeMaxDynamicSharedMemorySize,
                             smem_bytes);
        flash_attn<<<dim3((SS + 127) / 128, BH), 256, smem_bytes>>>(q, k, v, att);
    }

    // 4) output projection -> fp32 out
    h16_gemm_ldsm<<<dim3(HID / 128, (MROWS + 127) / 128), 256, gemm_smem>>>(
        (const __half*)att, wot, b_o, out, MROWS, HID, HID, 0);
}